// round 14
// baseline (speedup 1.0000x reference)
#include <cuda_runtime.h>
#include <cuda_bf16.h>
#include <cstdint>

// Conv2d 3x3 s1 p1 NCHW fp32 — implicit GEMM on mma.sync.m16n8k16 (bf16 3-split).
// R12 trunk (549us) + ONE change: A-staging balanced across all 8 warps
// (thread = pixel-half, 8 taps each); B cp.async spread across all 256 threads.
// x:[32,64,112,112] w:[128,64,3,3] b:[128] -> out:[32,128,112,112]

#define CHh 112
#define CWw 112
#define CCI 64
#define CKo 128
#define KTOT 576
#define TH 8
#define TW 16
#define RAW_RS 18
#define RAW_ICS 180
#define RAW_TOT 11520
#define KC 16
#define NCHUNK 36
#define TSTRIDE_B 48
#define TILE_B (128 * TSTRIDE_B)

#define OFF_KOFF 0
#define OFF_RAW  2304
#define OFF_A    48384
#define OFF_B    72960
#define SMEM_BYTES 97536
#define OFF_EPI  2304

__device__ uint32_t g_whi[NCHUNK * 128 * 8];  // [cc][oc][8] bf16x2 hi pairs (32B/row)
__device__ uint32_t g_wlo[NCHUNK * 128 * 8];

__device__ __forceinline__ uint32_t smem_u32(const void* p) {
    uint32_t a;
    asm("{ .reg .u64 t; cvta.to.shared.u64 t, %1; cvt.u32.u64 %0, t; }"
        : "=r"(a) : "l"(p));
    return a;
}
__device__ __forceinline__ void cp_async4(uint32_t dst, const void* src, bool ok) {
    int sz = ok ? 4 : 0;
    asm volatile("cp.async.ca.shared.global [%0], [%1], 4, %2;"
                 :: "r"(dst), "l"(src), "r"(sz));
}
__device__ __forceinline__ void cp_async16(uint32_t dst, const void* src) {
    asm volatile("cp.async.ca.shared.global [%0], [%1], 16;"
                 :: "r"(dst), "l"(src));
}
// split float pair -> packed bf16x2 hi + bf16x2 lo-residual (lane0 = v0)
__device__ __forceinline__ void split2(float v0, float v1, uint32_t& hp, uint32_t& lp) {
    asm("cvt.rn.bf16x2.f32 %0, %1, %2;" : "=r"(hp) : "f"(v1), "f"(v0));
    float h0 = __uint_as_float(hp << 16);
    float h1 = __uint_as_float(hp & 0xFFFF0000u);
    float l0 = v0 - h0, l1 = v1 - h1;
    asm("cvt.rn.bf16x2.f32 %0, %1, %2;" : "=r"(lp) : "f"(l1), "f"(l0));
}

#define LDSM4(r, addr) \
    asm volatile("ldmatrix.sync.aligned.m8n8.x4.shared.b16 {%0,%1,%2,%3}, [%4];" \
                 : "=r"((r)[0]), "=r"((r)[1]), "=r"((r)[2]), "=r"((r)[3]) : "r"(addr))

#define MMA16816(d, a, b0v, b1v) \
    asm volatile("mma.sync.aligned.m16n8k16.row.col.f32.bf16.bf16.f32 " \
                 "{%0,%1,%2,%3}, {%4,%5,%6,%7}, {%8,%9}, {%0,%1,%2,%3};" \
                 : "+f"((d)[0]), "+f"((d)[1]), "+f"((d)[2]), "+f"((d)[3]) \
                 : "r"((a)[0]), "r"((a)[1]), "r"((a)[2]), "r"((a)[3]), \
                   "r"(b0v), "r"(b1v))

// ---- pre-kernel: weights -> per-chunk bf16 hi/lo 32B rows ----
__global__ __launch_bounds__(256)
void convert_w_kernel(const float* __restrict__ wgt) {
    int t  = blockIdx.x * 256 + threadIdx.x;   // 36864 = 36*128*8
    int j  = t & 7;
    int oc = (t >> 3) & 127;
    int cc = t >> 10;
    float2 wv = *(const float2*)(wgt + (size_t)oc * KTOT + cc * KC + 2 * j);
    uint32_t hp, lp;
    split2(wv.x, wv.y, hp, lp);
    g_whi[t] = hp;
    g_wlo[t] = lp;
}

// -----------------------------------------------------------------------------

__global__ __launch_bounds__(256, 2)
void conv3x3_mma_kernel(const float* __restrict__ x,
                        const float* __restrict__ bias,
                        float* __restrict__ out) {
    extern __shared__ char smem[];
    const uint32_t sbase = smem_u32(smem);
    const int tid  = threadIdx.x;
    const int lane = tid & 31;
    const int wid  = tid >> 5;
    const int warp_m = wid & 3;
    const int warp_n = wid >> 2;

    const int ow0 = blockIdx.x * TW;
    const int oh0 = blockIdx.y * TH;
    const int n   = blockIdx.z;

    // tap-offset LUT
    int* koff = (int*)(smem + OFF_KOFF);
    for (int k = tid; k < KTOT; k += 256) {
        int ic = k / 9, t = k - ic * 9, kh = t / 3, kw = t - kh * 3;
        koff[k] = ic * RAW_ICS + kh * RAW_RS + kw;
    }

    // raw fp32 input tile via cp.async (zero-padded halo)
    const float* xn = x + (size_t)n * CCI * CHh * CWw;
    {
        const int h0 = oh0 - 1, w0 = ow0 - 1;
#pragma unroll 5
        for (int j = 0; j < RAW_TOT / 256; j++) {
            int idx = j * 256 + tid;
            int ic  = idx / RAW_ICS;
            int rem = idx - ic * RAW_ICS;
            int rr  = rem / RAW_RS;
            int c2  = rem - rr * RAW_RS;
            int gh = h0 + rr, gw = w0 + c2;
            bool ok = ((unsigned)gh < CHh) && ((unsigned)gw < CWw);
            const float* src = ok ? (xn + (size_t)ic * CHh * CWw + gh * CWw + gw) : xn;
            cp_async4(sbase + OFF_RAW + idx * 4, src, ok);
        }
        asm volatile("cp.async.commit_group;");
        asm volatile("cp.async.wait_group 0;");
    }
    __syncthreads();

    const float* sraw = (const float*)(smem + OFF_RAW);

    // balanced staging: thread = (pixel, half); every thread does 8 A-taps + 2 B-copies
    const int pix  = tid >> 1;
    const int half = tid & 1;
    const int prc  = (pix >> 4) * RAW_RS + (pix & 15);
    const int b_oc = tid & 127;
    const int b_sp = tid >> 7;        // 0=hi split, 1=lo split

    auto stage = [&](int cc, int buf) {
        {   // B: 2 x 16B per thread from pre-split weights (async, no stall)
            const uint32_t* src =
                (b_sp ? g_wlo : g_whi) + ((size_t)cc * 128 + b_oc) * 8;
            uint32_t db = sbase + OFF_B + (buf * 2 + b_sp) * TILE_B + b_oc * TSTRIDE_B;
            cp_async16(db,      src);
            cp_async16(db + 16, src + 4);
        }
        {   // A: 8 taps for this (pixel, half)
            const int kbase = cc * KC + half * 8;
            float v[8];
#pragma unroll
            for (int kk = 0; kk < 8; kk++)
                v[kk] = sraw[koff[kbase + kk] + prc];
            uint32_t hp[4], lp[4];
#pragma unroll
            for (int i = 0; i < 4; i++) split2(v[2 * i], v[2 * i + 1], hp[i], lp[i]);
            uint32_t da = sbase + OFF_A + pix * TSTRIDE_B + half * 16;
            asm volatile("st.shared.v4.b32 [%0], {%1,%2,%3,%4};"
                         :: "r"(da + (buf * 2 + 0) * TILE_B),
                            "r"(hp[0]), "r"(hp[1]), "r"(hp[2]), "r"(hp[3]));
            asm volatile("st.shared.v4.b32 [%0], {%1,%2,%3,%4};"
                         :: "r"(da + (buf * 2 + 1) * TILE_B),
                            "r"(lp[0]), "r"(lp[1]), "r"(lp[2]), "r"(lp[3]));
        }
        asm volatile("cp.async.commit_group;");
    };

    // ldmatrix per-lane offsets (48B stride: r*3 mod 8 is a permutation -> conflict-free)
    uint32_t a_off[2], b_off[4];
#pragma unroll
    for (int mi = 0; mi < 2; mi++)
        a_off[mi] = (uint32_t)((warp_m * 32 + mi * 16 + (lane & 15)) * TSTRIDE_B
                               + ((lane >> 4) << 4));
#pragma unroll
    for (int nt = 0; nt < 4; nt++)
        b_off[nt] = (uint32_t)((warp_n * 64 + nt * 16 + (lane & 15)) * TSTRIDE_B
                               + ((lane >> 4) << 4));

    float acc[2][8][4];
#pragma unroll
    for (int mi = 0; mi < 2; mi++)
#pragma unroll
        for (int ni = 0; ni < 8; ni++)
#pragma unroll
            for (int e = 0; e < 4; e++) acc[mi][ni][e] = 0.0f;

    stage(0, 0);
    asm volatile("cp.async.wait_group 0;");
    __syncthreads();

    for (int cc = 0; cc < NCHUNK; cc++) {
        const int buf = cc & 1;
        if (cc + 1 < NCHUNK) stage(cc + 1, buf ^ 1);   // overlap with mma below

        uint32_t afr[2][2][4];                         // [split][mi]
#pragma unroll
        for (int s = 0; s < 2; s++)
#pragma unroll
            for (int mi = 0; mi < 2; mi++)
                LDSM4(afr[s][mi], sbase + OFF_A + (buf * 2 + s) * TILE_B + a_off[mi]);

#pragma unroll
        for (int nt = 0; nt < 4; nt++) {
            uint32_t bhf[4], blf[4];
            LDSM4(bhf, sbase + OFF_B + (buf * 2 + 0) * TILE_B + b_off[nt]);
            LDSM4(blf, sbase + OFF_B + (buf * 2 + 1) * TILE_B + b_off[nt]);
#pragma unroll
            for (int h = 0; h < 2; h++) {
                uint32_t bh0 = bhf[h], bh1 = bhf[h + 2];
                uint32_t bl0 = blf[h], bl1 = blf[h + 2];
#pragma unroll
                for (int mi = 0; mi < 2; mi++) {
                    float* d = acc[mi][nt * 2 + h];
                    MMA16816(d, afr[0][mi], bh0, bh1);   // Ahi.Bhi
                    MMA16816(d, afr[0][mi], bl0, bl1);   // Ahi.Blo
                    MMA16816(d, afr[1][mi], bh0, bh1);   // Alo.Bhi
                }
            }
        }
        asm volatile("cp.async.wait_group 0;");        // next chunk's B landed
        __syncthreads();
    }

    // epilogue: transpose through smem, coalesced float4 stores with bias
    float* se = (float*)(smem + OFF_EPI);          // [128 oc][132]
#pragma unroll
    for (int mi = 0; mi < 2; mi++)
#pragma unroll
        for (int ni = 0; ni < 8; ni++) {
            int p0 = warp_m * 32 + mi * 16 + (lane >> 2);
            int q0 = warp_n * 64 + ni * 8 + (lane & 3) * 2;
            se[q0 * 132 + p0]           = acc[mi][ni][0];
            se[(q0 + 1) * 132 + p0]     = acc[mi][ni][1];
            se[q0 * 132 + p0 + 8]       = acc[mi][ni][2];
            se[(q0 + 1) * 132 + p0 + 8] = acc[mi][ni][3];
        }
    __syncthreads();

#pragma unroll
    for (int it = 0; it < 16; it++) {
        int i  = it * 256 + tid;
        int oc = i >> 5;
        int rem = i & 31;
        int rr = rem >> 2, c4 = rem & 3;
        float4 v = *(const float4*)(se + oc * 132 + rr * 16 + c4 * 4);
        float b = bias[oc];
        v.x += b; v.y += b; v.z += b; v.w += b;
        *(float4*)(out + (((size_t)n * CKo + oc) * CHh + oh0 + rr) * CWw + ow0 + c4 * 4) = v;
    }
}

extern "C" void kernel_launch(void* const* d_in, const int* in_sizes, int n_in,
                              void* d_out, int out_size) {
    const float* x    = (const float*)d_in[0];
    const float* wgt  = (const float*)d_in[1];
    const float* bias = (const float*)d_in[2];
    float* out        = (float*)d_out;

    cudaFuncSetAttribute(conv3x3_mma_kernel,
                         cudaFuncAttributeMaxDynamicSharedMemorySize, SMEM_BYTES);

    convert_w_kernel<<<NCHUNK * 128 * 8 / 256, 256>>>(wgt);   // 144 blocks, ~3us

    dim3 grid(CWw / TW, CHh / TH, 32);
    conv3x3_mma_kernel<<<grid, 256, SMEM_BYTES>>>(x, bias, out);
}

// round 16
// speedup vs baseline: 1.3895x; 1.3895x over previous
#include <cuda_runtime.h>
#include <cuda_fp16.h>
#include <cstdint>

// Conv2d 3x3 s1 p1 NCHW fp32 — implicit GEMM on mma.sync.m16n8k16 (fp16 2-term:
// A 1-split fp16, B 2-split fp16 hi/lo). R12 asymmetric-staging trunk.
// x:[32,64,112,112] w:[128,64,3,3] b:[128] -> out:[32,128,112,112]

#define CHh 112
#define CWw 112
#define CCI 64
#define CKo 128
#define KTOT 576
#define TH 8
#define TW 16
#define RAW_RS 18
#define RAW_ICS 180
#define RAW_TOT 11520
#define KC 16
#define NCHUNK 36
#define TSTRIDE_B 48
#define TILE_B (128 * TSTRIDE_B)

#define OFF_KOFF 0
#define OFF_RAW  2304
#define OFF_A    48384                    // [2 buf] * TILE_B          = 12288
#define OFF_B    60672                    // [2 buf][2 split] * TILE_B = 24576
#define SMEM_BYTES 85248
#define OFF_EPI  2304

__device__ uint32_t g_whi[NCHUNK * 128 * 8];  // [cc][oc][8] fp16x2 hi pairs (32B/row)
__device__ uint32_t g_wlo[NCHUNK * 128 * 8];  // fp16x2 lo-residual pairs

__device__ __forceinline__ uint32_t smem_u32(const void* p) {
    uint32_t a;
    asm("{ .reg .u64 t; cvta.to.shared.u64 t, %1; cvt.u32.u64 %0, t; }"
        : "=r"(a) : "l"(p));
    return a;
}
__device__ __forceinline__ void cp_async4(uint32_t dst, const void* src, bool ok) {
    int sz = ok ? 4 : 0;
    asm volatile("cp.async.ca.shared.global [%0], [%1], 4, %2;"
                 :: "r"(dst), "l"(src), "r"(sz));
}
__device__ __forceinline__ void cp_async16(uint32_t dst, const void* src) {
    asm volatile("cp.async.ca.shared.global [%0], [%1], 16;"
                 :: "r"(dst), "l"(src));
}
// pack two floats into fp16x2 (lane0 = v0), round-to-nearest
__device__ __forceinline__ uint32_t pack_h2(float v0, float v1) {
    uint32_t p;
    asm("cvt.rn.f16x2.f32 %0, %1, %2;" : "=r"(p) : "f"(v1), "f"(v0));
    return p;
}

#define LDSM4(r, addr) \
    asm volatile("ldmatrix.sync.aligned.m8n8.x4.shared.b16 {%0,%1,%2,%3}, [%4];" \
                 : "=r"((r)[0]), "=r"((r)[1]), "=r"((r)[2]), "=r"((r)[3]) : "r"(addr))

#define MMA16816(d, a, b0v, b1v) \
    asm volatile("mma.sync.aligned.m16n8k16.row.col.f32.f16.f16.f32 " \
                 "{%0,%1,%2,%3}, {%4,%5,%6,%7}, {%8,%9}, {%0,%1,%2,%3};" \
                 : "+f"((d)[0]), "+f"((d)[1]), "+f"((d)[2]), "+f"((d)[3]) \
                 : "r"((a)[0]), "r"((a)[1]), "r"((a)[2]), "r"((a)[3]), \
                   "r"(b0v), "r"(b1v))

// ---- pre-kernel: weights -> per-chunk fp16 hi + fp16 lo-residual 32B rows ----
__global__ __launch_bounds__(256)
void convert_w_kernel(const float* __restrict__ wgt) {
    int t  = blockIdx.x * 256 + threadIdx.x;   // 36864 = 36*128*8
    int j  = t & 7;
    int oc = (t >> 3) & 127;
    int cc = t >> 10;
    float2 wv = *(const float2*)(wgt + (size_t)oc * KTOT + cc * KC + 2 * j);
    uint32_t hp = pack_h2(wv.x, wv.y);
    __half2 h2 = *(__half2*)&hp;
    float r0 = wv.x - __low2float(h2);
    float r1 = wv.y - __high2float(h2);
    g_whi[t] = hp;
    g_wlo[t] = pack_h2(r0, r1);
}

// -----------------------------------------------------------------------------

__global__ __launch_bounds__(256, 2)
void conv3x3_mma_kernel(const float* __restrict__ x,
                        const float* __restrict__ bias,
                        float* __restrict__ out) {
    extern __shared__ char smem[];
    const uint32_t sbase = smem_u32(smem);
    const int tid  = threadIdx.x;
    const int lane = tid & 31;
    const int wid  = tid >> 5;
    const int warp_m = wid & 3;
    const int warp_n = wid >> 2;

    const int ow0 = blockIdx.x * TW;
    const int oh0 = blockIdx.y * TH;
    const int n   = blockIdx.z;

    // tap-offset LUT
    int* koff = (int*)(smem + OFF_KOFF);
    for (int k = tid; k < KTOT; k += 256) {
        int ic = k / 9, t = k - ic * 9, kh = t / 3, kw = t - kh * 3;
        koff[k] = ic * RAW_ICS + kh * RAW_RS + kw;
    }

    // raw fp32 input tile via cp.async (zero-padded halo)
    const float* xn = x + (size_t)n * CCI * CHh * CWw;
    {
        const int h0 = oh0 - 1, w0 = ow0 - 1;
#pragma unroll 5
        for (int j = 0; j < RAW_TOT / 256; j++) {
            int idx = j * 256 + tid;
            int ic  = idx / RAW_ICS;
            int rem = idx - ic * RAW_ICS;
            int rr  = rem / RAW_RS;
            int c2  = rem - rr * RAW_RS;
            int gh = h0 + rr, gw = w0 + c2;
            bool ok = ((unsigned)gh < CHh) && ((unsigned)gw < CWw);
            const float* src = ok ? (xn + (size_t)ic * CHh * CWw + gh * CWw + gw) : xn;
            cp_async4(sbase + OFF_RAW + idx * 4, src, ok);
        }
        asm volatile("cp.async.commit_group;");
        asm volatile("cp.async.wait_group 0;");
    }
    __syncthreads();

    const float* sraw = (const float*)(smem + OFF_RAW);

    // asymmetric staging (R12 scheme): warps 0-3 build A (1 thread = 1 pixel, fp16
    // 1-split); warps 4-7 issue 4x cp.async.16B for B hi/lo from pre-split weights.
    const int st_pix = tid & 127;
    const int st_prc = (st_pix >> 4) * RAW_RS + (st_pix & 15);

    auto stage = [&](int cc, int buf) {
        const int kbase = cc * KC;
        if (tid < 128) {                            // A: one pixel, 16 taps, fp16 pack
            float v[KC];
#pragma unroll
            for (int kk = 0; kk < KC; kk++)
                v[kk] = sraw[koff[kbase + kk] + st_prc];
            uint32_t hp[8];
#pragma unroll
            for (int i = 0; i < 8; i++) hp[i] = pack_h2(v[2 * i], v[2 * i + 1]);
            uint32_t da = sbase + OFF_A + buf * TILE_B + st_pix * TSTRIDE_B;
            asm volatile("st.shared.v4.b32 [%0], {%1,%2,%3,%4};" :: "r"(da),
                         "r"(hp[0]), "r"(hp[1]), "r"(hp[2]), "r"(hp[3]));
            asm volatile("st.shared.v4.b32 [%0], {%1,%2,%3,%4};" :: "r"(da + 16),
                         "r"(hp[4]), "r"(hp[5]), "r"(hp[6]), "r"(hp[7]));
        } else {                                    // B: one oc row, hi+lo, 4x16B async
            const uint32_t* shi = g_whi + ((size_t)cc * 128 + st_pix) * 8;
            const uint32_t* slo = g_wlo + ((size_t)cc * 128 + st_pix) * 8;
            uint32_t bh = sbase + OFF_B + (buf * 2 + 0) * TILE_B + st_pix * TSTRIDE_B;
            uint32_t bl = sbase + OFF_B + (buf * 2 + 1) * TILE_B + st_pix * TSTRIDE_B;
            cp_async16(bh,      shi);
            cp_async16(bh + 16, shi + 4);
            cp_async16(bl,      slo);
            cp_async16(bl + 16, slo + 4);
        }
        asm volatile("cp.async.commit_group;");
    };

    // ldmatrix per-lane offsets (48B stride: r*3 mod 8 is a permutation -> conflict-free)
    uint32_t a_off[2], b_off[4];
#pragma unroll
    for (int mi = 0; mi < 2; mi++)
        a_off[mi] = (uint32_t)((warp_m * 32 + mi * 16 + (lane & 15)) * TSTRIDE_B
                               + ((lane >> 4) << 4));
#pragma unroll
    for (int nt = 0; nt < 4; nt++)
        b_off[nt] = (uint32_t)((warp_n * 64 + nt * 16 + (lane & 15)) * TSTRIDE_B
                               + ((lane >> 4) << 4));

    float acc[2][8][4];
#pragma unroll
    for (int mi = 0; mi < 2; mi++)
#pragma unroll
        for (int ni = 0; ni < 8; ni++)
#pragma unroll
            for (int e = 0; e < 4; e++) acc[mi][ni][e] = 0.0f;

    stage(0, 0);
    asm volatile("cp.async.wait_group 0;");
    __syncthreads();

    for (int cc = 0; cc < NCHUNK; cc++) {
        const int buf = cc & 1;
        if (cc + 1 < NCHUNK) stage(cc + 1, buf ^ 1);   // overlap with mma below

        uint32_t afr[2][4];                            // [mi] single split
#pragma unroll
        for (int mi = 0; mi < 2; mi++)
            LDSM4(afr[mi], sbase + OFF_A + buf * TILE_B + a_off[mi]);

#pragma unroll
        for (int nt = 0; nt < 4; nt++) {
            uint32_t bhf[4], blf[4];
            LDSM4(bhf, sbase + OFF_B + (buf * 2 + 0) * TILE_B + b_off[nt]);
            LDSM4(blf, sbase + OFF_B + (buf * 2 + 1) * TILE_B + b_off[nt]);
#pragma unroll
            for (int h = 0; h < 2; h++) {
                uint32_t bh0 = bhf[h], bh1 = bhf[h + 2];
                uint32_t bl0 = blf[h], bl1 = blf[h + 2];
#pragma unroll
                for (int mi = 0; mi < 2; mi++) {
                    float* d = acc[mi][nt * 2 + h];
                    MMA16816(d, afr[mi], bh0, bh1);   // A . Bhi
                    MMA16816(d, afr[mi], bl0, bl1);   // A . Blo
                }
            }
        }
        asm volatile("cp.async.wait_group 0;");        // next chunk's B landed
        __syncthreads();
    }

    // epilogue: transpose through smem, coalesced float4 stores with bias
    float* se = (float*)(smem + OFF_EPI);          // [128 oc][132]
#pragma unroll
    for (int mi = 0; mi < 2; mi++)
#pragma unroll
        for (int ni = 0; ni < 8; ni++) {
            int p0 = warp_m * 32 + mi * 16 + (lane >> 2);
            int q0 = warp_n * 64 + ni * 8 + (lane & 3) * 2;
            se[q0 * 132 + p0]           = acc[mi][ni][0];
            se[(q0 + 1) * 132 + p0]     = acc[mi][ni][1];
            se[q0 * 132 + p0 + 8]       = acc[mi][ni][2];
            se[(q0 + 1) * 132 + p0 + 8] = acc[mi][ni][3];
        }
    __syncthreads();

#pragma unroll
    for (int it = 0; it < 16; it++) {
        int i  = it * 256 + tid;
        int oc = i >> 5;
        int rem = i & 31;
        int rr = rem >> 2, c4 = rem & 3;
        float4 v = *(const float4*)(se + oc * 132 + rr * 16 + c4 * 4);
        float b = bias[oc];
        v.x += b; v.y += b; v.z += b; v.w += b;
        *(float4*)(out + (((size_t)n * CKo + oc) * CHh + oh0 + rr) * CWw + ow0 + c4 * 4) = v;
    }
}

extern "C" void kernel_launch(void* const* d_in, const int* in_sizes, int n_in,
                              void* d_out, int out_size) {
    const float* x    = (const float*)d_in[0];
    const float* wgt  = (const float*)d_in[1];
    const float* bias = (const float*)d_in[2];
    float* out        = (float*)d_out;

    cudaFuncSetAttribute(conv3x3_mma_kernel,
                         cudaFuncAttributeMaxDynamicSharedMemorySize, SMEM_BYTES);

    convert_w_kernel<<<NCHUNK * 128 * 8 / 256, 256>>>(wgt);   // 144 blocks, ~3us

    dim3 grid(CWw / TW, CHh / TH, 32);
    conv3x3_mma_kernel<<<grid, 256, SMEM_BYTES>>>(x, bias, out);
}